// round 9
// baseline (speedup 1.0000x reference)
#include <cuda_runtime.h>
#include <cuda_fp16.h>
#include <cuda_pipeline.h>
#include <cstdint>

// ============================================================================
// BlockConvolutionLean, fp16 mma.sync, fused A-conversion, 2 CTAs/SM,
// coalesced epilogue through smem:
//   out = segmented-exclusive-cumsum_8( A @ W^T ) + b_eff, b_eff[0]=2*bias[0]
// - W fp16 (pre-converted micro-kernel), CTA's 128xK tile smem-resident.
// - A: full-line LDG.128 -> cvt f16x2 -> swizzled STS -> ldmatrix; 2-stage.
// - Epilogue: scan in regs -> swizzled STS fp32 tile -> coalesced LDS.128 ->
//   full-row STG.128 (4 wavefronts/instr instead of 8).
// ============================================================================

#define MROWS 65536
#define KD 256
#define ND 256
#define BM 128
#define BN 128
#define THREADS 256
#define NCH 4                          // K chunks of 64

#define W_REGION 16384                 // 128 rows x 128B (one K=64 chunk)
#define OFF_A (4 * W_REGION)           // 65536: W resident (4 regions)
#define A_STAGE 16384                  // 128 rows x 128B
#define SMEM_TOTAL (OFF_A + 2 * A_STAGE)   // 98304 B -> 2 CTAs = 192KB

__device__ __half g_Whf[ND * KD];      // W fp16

// ---------------------------------------------------------------------------
__device__ __forceinline__ uint32_t smem_u32(const void* p) {
    uint32_t a;
    asm("{ .reg .u64 t; cvta.to.shared.u64 t, %1; cvt.u32.u64 %0, t; }"
        : "=r"(a) : "l"(p));
    return a;
}
__device__ __forceinline__ void ldsm_x4(uint32_t* r, uint32_t addr) {
    asm volatile("ldmatrix.sync.aligned.m8n8.x4.shared.b16 {%0,%1,%2,%3}, [%4];"
                 : "=r"(r[0]), "=r"(r[1]), "=r"(r[2]), "=r"(r[3]) : "r"(addr));
}
__device__ __forceinline__ void mma_f16(float* c, const uint32_t* a, const uint32_t* b) {
    asm volatile("mma.sync.aligned.m16n8k16.row.col.f32.f16.f16.f32 "
                 "{%0,%1,%2,%3}, {%4,%5,%6,%7}, {%8,%9}, {%0,%1,%2,%3};"
                 : "+f"(c[0]), "+f"(c[1]), "+f"(c[2]), "+f"(c[3])
                 : "r"(a[0]), "r"(a[1]), "r"(a[2]), "r"(a[3]), "r"(b[0]), "r"(b[1]));
}
__device__ __forceinline__ uint32_t h2u(__half2 h) {
    return *reinterpret_cast<uint32_t*>(&h);
}
__device__ __forceinline__ uint2 cvt2(float4 v) {
    __half2 h0 = __floats2half2_rn(v.x, v.y);
    __half2 h1 = __floats2half2_rn(v.z, v.w);
    return make_uint2(h2u(h0), h2u(h1));
}

// ---------------------------------------------------------------------------
__global__ __launch_bounds__(256) void convert_W(const float* __restrict__ W) {
    int i = (blockIdx.x * 256 + threadIdx.x) * 4;
    float4 v = *reinterpret_cast<const float4*>(W + i);
    uint2 u = cvt2(v);
    *reinterpret_cast<uint2*>(g_Whf + i) = u;
}

// ---------------------------------------------------------------------------
__global__ __launch_bounds__(THREADS, 2)
void bc_mma(const float* __restrict__ A, const float* __restrict__ bias,
            float* __restrict__ out)
{
    extern __shared__ __align__(1024) char smem[];
    const int tid = threadIdx.x;
    const int lane = tid & 31, w = tid >> 5;
    const int wm = w >> 2, wn = w & 3;         // 2(m) x 4(n); warp tile 64 x 32
    const int n0 = blockIdx.x * BN;            // fast dim (2) -> A L2 reuse
    const int m0 = blockIdx.y * BM;

    // ---- prologue: W tile (128 x K=256 fp16, 4 swizzled regions) ----
#pragma unroll
    for (int i = 0; i < 16; i++) {
        int v = tid + i * THREADS;             // 0..4095
        int c = v >> 10;                       // region 0..3
        int r = (v >> 3) & 127;                // W row 0..127
        int seg = v & 7;
        uint32_t off = (uint32_t)c * W_REGION + (uint32_t)r * 128 +
                       (uint32_t)((seg * 16) ^ ((r & 7) << 4));
        __pipeline_memcpy_async(smem + off,
                                g_Whf + (size_t)(n0 + r) * KD + c * 64 + seg * 8, 16);
    }
    __pipeline_commit();

    // ---- A chunk 0: LDG full-line -> cvt -> STS stage 0 ----
    const int rbase = w * 16 + (lane >> 4);
    const float* ag = A + (size_t)(m0 + rbase) * KD + (lane & 15) * 4;
    const uint32_t stscol = (uint32_t)(lane & 15) * 8;

    {
        uint2 pc[8];
#pragma unroll
        for (int j = 0; j < 8; j++)
            pc[j] = cvt2(*reinterpret_cast<const float4*>(ag + j * 2 * KD));
#pragma unroll
        for (int j = 0; j < 8; j++) {
            int row = rbase + 2 * j;
            uint32_t off = (uint32_t)row * 128 + (stscol ^ (uint32_t)((row & 7) << 4));
            *reinterpret_cast<uint2*>(smem + OFF_A + off) = pc[j];
        }
    }

    float acc[4][4][4] = {};

    const uint32_t sb = smem_u32(smem);
    const uint32_t xorv   = (uint32_t)(lane & 7) << 4;
    const uint32_t a_row  = (uint32_t)(wm * 64 + (lane & 15));
    const uint32_t a_csel = ((uint32_t)(lane >> 4)) << 4;
    const uint32_t b_row  = (uint32_t)(wn * 32 + ((lane >> 4) << 3) + (lane & 7));
    const uint32_t b_csel = ((uint32_t)((lane >> 3) & 1)) << 4;

    __pipeline_wait_prior(0);
    __syncthreads();

    // ---- mainloop: 4 chunks x 4 k-steps, 2-stage A, 1 sync per chunk ----
#pragma unroll
    for (int c = 0; c < NCH; c++) {
        const uint32_t abase = sb + OFF_A + (uint32_t)(c & 1) * A_STAGE;
        const uint32_t wbase = sb + (uint32_t)c * W_REGION;
        char* nstage = smem + OFF_A + ((c + 1) & 1) * A_STAGE;

        float4 pf[4];
        if (c < NCH - 1) {
#pragma unroll
            for (int j = 0; j < 4; j++)
                pf[j] = *reinterpret_cast<const float4*>(
                    ag + (c + 1) * 64 + j * 2 * KD);
        }

#pragma unroll
        for (int s = 0; s < 2; s++) {
            const uint32_t ksa = (((uint32_t)s * 32) + a_csel) ^ xorv;
            const uint32_t ksb = (((uint32_t)s * 32) + b_csel) ^ xorv;
            uint32_t a[4][4], b[2][4];
#pragma unroll
            for (int mf = 0; mf < 4; mf++)
                ldsm_x4(a[mf], abase + (a_row + mf * 16) * 128 + ksa);
#pragma unroll
            for (int nfp = 0; nfp < 2; nfp++)
                ldsm_x4(b[nfp], wbase + (b_row + nfp * 16) * 128 + ksb);
#pragma unroll
            for (int mf = 0; mf < 4; mf++)
#pragma unroll
                for (int nfp = 0; nfp < 2; nfp++) {
                    mma_f16(acc[mf][2 * nfp],     a[mf], b[nfp]);
                    mma_f16(acc[mf][2 * nfp + 1], a[mf], b[nfp] + 2);
                }
        }

        if (c < NCH - 1) {
#pragma unroll
            for (int j = 0; j < 4; j++) {
                int row = rbase + 2 * j;
                uint32_t off = (uint32_t)row * 128 +
                               (stscol ^ (uint32_t)((row & 7) << 4));
                *reinterpret_cast<uint2*>(nstage + off) = cvt2(pf[j]);
            }
#pragma unroll
            for (int j = 0; j < 4; j++)
                pf[j] = *reinterpret_cast<const float4*>(
                    ag + (c + 1) * 64 + (4 + j) * 2 * KD);
        }

#pragma unroll
        for (int s = 2; s < 4; s++) {
            const uint32_t ksa = (((uint32_t)s * 32) + a_csel) ^ xorv;
            const uint32_t ksb = (((uint32_t)s * 32) + b_csel) ^ xorv;
            uint32_t a[4][4], b[2][4];
#pragma unroll
            for (int mf = 0; mf < 4; mf++)
                ldsm_x4(a[mf], abase + (a_row + mf * 16) * 128 + ksa);
#pragma unroll
            for (int nfp = 0; nfp < 2; nfp++)
                ldsm_x4(b[nfp], wbase + (b_row + nfp * 16) * 128 + ksb);
#pragma unroll
            for (int mf = 0; mf < 4; mf++)
#pragma unroll
                for (int nfp = 0; nfp < 2; nfp++) {
                    mma_f16(acc[mf][2 * nfp],     a[mf], b[nfp]);
                    mma_f16(acc[mf][2 * nfp + 1], a[mf], b[nfp] + 2);
                }
        }

        if (c < NCH - 1) {
#pragma unroll
            for (int j = 0; j < 4; j++) {
                int row = rbase + 2 * (4 + j);
                uint32_t off = (uint32_t)row * 128 +
                               (stscol ^ (uint32_t)((row & 7) << 4));
                *reinterpret_cast<uint2*>(nstage + off) = cvt2(pf[j]);
            }
            __syncthreads();
        }
    }

    // ---- epilogue ----
    // Scan in regs, then route the 128x128 fp32 tile through smem so global
    // stores are full contiguous 512B rows.
    const int p = lane >> 2;                   // block position 0..7
    float be = __ldg(bias + p);
    if (p == 0) be += be;                      // b_eff[0] = 2*bias[0]

    __syncthreads();   // all mainloop smem reads done -> safe to repurpose

    // Swizzled fp32 tile at smem offset 0: row stride 512B, xor (row&7)<<5.
#pragma unroll
    for (int mf = 0; mf < 4; mf++) {
#pragma unroll
        for (int nf = 0; nf < 4; nf++) {
            float e[4];
#pragma unroll
            for (int q = 0; q < 4; q++) {
                float v = acc[mf][nf][q];
                float sgm = v, t;
                t = __shfl_up_sync(0xffffffffu, sgm, 4);  if (p >= 1) sgm += t;
                t = __shfl_up_sync(0xffffffffu, sgm, 8);  if (p >= 2) sgm += t;
                t = __shfl_up_sync(0xffffffffu, sgm, 16); if (p >= 4) sgm += t;
                e[q] = sgm - v + be;
            }
            const int r0  = wm * 64 + mf * 16 + p;       // CTA-local row
            const uint32_t colb = (uint32_t)(wn * 32 + nf * 8 + (lane & 3) * 2) * 4;
            uint32_t o0 = (uint32_t)r0 * 512 + (colb ^ (uint32_t)((r0 & 7) << 5));
            *reinterpret_cast<float2*>(smem + o0) = make_float2(e[0], e[1]);
            const int r1 = r0 + 8;
            uint32_t o1 = (uint32_t)r1 * 512 + (colb ^ (uint32_t)((r1 & 7) << 5));
            *reinterpret_cast<float2*>(smem + o1) = make_float2(e[2], e[3]);
        }
    }
    __syncthreads();

    // Coalesced flush: each warp-instr covers one full 512B row.
#pragma unroll
    for (int i = 0; i < 16; i++) {
        int v = tid + i * THREADS;             // 0..4095
        int row = v >> 5;                      // 0..127
        int cg  = v & 31;                      // 16B col group
        uint32_t off = (uint32_t)row * 512 +
                       (uint32_t)((cg * 16) ^ ((row & 7) << 5));
        float4 val = *reinterpret_cast<const float4*>(smem + off);
        *reinterpret_cast<float4*>(
            out + (size_t)(m0 + row) * ND + n0 + cg * 4) = val;
    }
}

// ---------------------------------------------------------------------------
extern "C" void kernel_launch(void* const* d_in, const int* in_sizes, int n_in,
                              void* d_out, int out_size)
{
    const float* A    = (const float*)d_in[0];   // [65536, 256]
    const float* W    = (const float*)d_in[1];   // [256, 256]
    const float* bias = (const float*)d_in[2];   // [8]
    float* out = (float*)d_out;

    convert_W<<<(ND * KD) / (4 * 256), 256>>>(W);

    cudaFuncSetAttribute(bc_mma, cudaFuncAttributeMaxDynamicSharedMemorySize,
                         SMEM_TOTAL);
    dim3 grid(ND / BN, MROWS / BM);              // (2, 512)
    bc_mma<<<grid, THREADS, SMEM_TOTAL>>>(A, bias, out);
    (void)in_sizes; (void)n_in; (void)out_size;
}

// round 10
// speedup vs baseline: 1.0818x; 1.0818x over previous
#include <cuda_runtime.h>
#include <cuda_fp16.h>
#include <cstdint>

// ============================================================================
// BlockConvolutionLean, fp16 mma.sync, single fused kernel (no pre-passes):
//   out = segmented-exclusive-cumsum_8( A @ W^T ) + b_eff, b_eff[0]=2*bias[0]
// - W: fp32 LDG (L2-resident) -> cvt -> swizzled STS in CTA prologue.
// - A: full-line LDG.128 -> cvt f16x2 -> swizzled STS -> ldmatrix; 2-stage,
//   one __syncthreads per K-chunk.
// - BN=128 => acc 64 regs/thread => 2 CTAs/SM (16 warps).
// - Epilogue: in-register segmented exclusive scan (3 shfl) + direct STG.
// ============================================================================

#define MROWS 65536
#define KD 256
#define ND 256
#define BM 128
#define BN 128
#define THREADS 256
#define NCH 4                          // K chunks of 64

#define W_REGION 16384                 // 128 rows x 128B (one K=64 chunk)
#define OFF_A (4 * W_REGION)           // 65536: W resident (4 regions)
#define A_STAGE 16384                  // 128 rows x 128B
#define SMEM_TOTAL (OFF_A + 2 * A_STAGE)   // 98304 B -> 2 CTAs = 192KB

// ---------------------------------------------------------------------------
__device__ __forceinline__ uint32_t smem_u32(const void* p) {
    uint32_t a;
    asm("{ .reg .u64 t; cvta.to.shared.u64 t, %1; cvt.u32.u64 %0, t; }"
        : "=r"(a) : "l"(p));
    return a;
}
__device__ __forceinline__ void ldsm_x4(uint32_t* r, uint32_t addr) {
    asm volatile("ldmatrix.sync.aligned.m8n8.x4.shared.b16 {%0,%1,%2,%3}, [%4];"
                 : "=r"(r[0]), "=r"(r[1]), "=r"(r[2]), "=r"(r[3]) : "r"(addr));
}
__device__ __forceinline__ void mma_f16(float* c, const uint32_t* a, const uint32_t* b) {
    asm volatile("mma.sync.aligned.m16n8k16.row.col.f32.f16.f16.f32 "
                 "{%0,%1,%2,%3}, {%4,%5,%6,%7}, {%8,%9}, {%0,%1,%2,%3};"
                 : "+f"(c[0]), "+f"(c[1]), "+f"(c[2]), "+f"(c[3])
                 : "r"(a[0]), "r"(a[1]), "r"(a[2]), "r"(a[3]), "r"(b[0]), "r"(b[1]));
}
__device__ __forceinline__ uint32_t h2u(__half2 h) {
    return *reinterpret_cast<uint32_t*>(&h);
}
__device__ __forceinline__ uint2 cvt2(float4 v) {
    __half2 h0 = __floats2half2_rn(v.x, v.y);
    __half2 h1 = __floats2half2_rn(v.z, v.w);
    return make_uint2(h2u(h0), h2u(h1));
}

// ---------------------------------------------------------------------------
__global__ __launch_bounds__(THREADS, 2)
void bc_mma(const float* __restrict__ A, const float* __restrict__ W,
            const float* __restrict__ bias, float* __restrict__ out)
{
    extern __shared__ __align__(1024) char smem[];
    const int tid = threadIdx.x;
    const int lane = tid & 31, w = tid >> 5;
    const int wm = w >> 2, wn = w & 3;         // 2(m) x 4(n); warp tile 64 x 32
    const int n0 = blockIdx.x * BN;            // fast dim (2) -> A L2 reuse
    const int m0 = blockIdx.y * BM;

    // ---- prologue part 1: W tile fp32 -> fp16, swizzled (4 K-regions) ----
    // 128 rows x 64 float4/row = 8192 float4 / 256 thr = 32 each; coalesced.
    {
        const float* wg = W + (size_t)n0 * KD;
#pragma unroll
        for (int i = 0; i < 32; i++) {
            int v = tid + i * THREADS;         // 0..8191
            int r = v >> 6;                    // W row 0..127
            int f4 = v & 63;                   // float4 index within row
            float4 wv = *reinterpret_cast<const float4*>(
                wg + (size_t)r * KD + f4 * 4);
            int c = f4 >> 4;                   // region 0..3
            uint32_t col = (uint32_t)(f4 & 15) * 8;
            uint32_t off = (uint32_t)c * W_REGION + (uint32_t)r * 128 +
                           (col ^ (uint32_t)((r & 7) << 4));
            *reinterpret_cast<uint2*>(smem + off) = cvt2(wv);
        }
    }

    // ---- prologue part 2: A chunk 0 LDG -> cvt -> STS stage 0 ----
    const int rbase = w * 16 + (lane >> 4);
    const float* ag = A + (size_t)(m0 + rbase) * KD + (lane & 15) * 4;
    const uint32_t stscol = (uint32_t)(lane & 15) * 8;

    {
        uint2 pc[8];
#pragma unroll
        for (int j = 0; j < 8; j++)
            pc[j] = cvt2(*reinterpret_cast<const float4*>(ag + j * 2 * KD));
#pragma unroll
        for (int j = 0; j < 8; j++) {
            int row = rbase + 2 * j;
            uint32_t off = (uint32_t)row * 128 + (stscol ^ (uint32_t)((row & 7) << 4));
            *reinterpret_cast<uint2*>(smem + OFF_A + off) = pc[j];
        }
    }

    float acc[4][4][4] = {};

    const uint32_t sb = smem_u32(smem);
    const uint32_t xorv   = (uint32_t)(lane & 7) << 4;
    const uint32_t a_row  = (uint32_t)(wm * 64 + (lane & 15));
    const uint32_t a_csel = ((uint32_t)(lane >> 4)) << 4;
    const uint32_t b_row  = (uint32_t)(wn * 32 + ((lane >> 4) << 3) + (lane & 7));
    const uint32_t b_csel = ((uint32_t)((lane >> 3) & 1)) << 4;

    __syncthreads();

    // ---- mainloop: 4 chunks x 4 k-steps, 2-stage A, 1 sync per chunk ----
#pragma unroll
    for (int c = 0; c < NCH; c++) {
        const uint32_t abase = sb + OFF_A + (uint32_t)(c & 1) * A_STAGE;
        const uint32_t wbase = sb + (uint32_t)c * W_REGION;
        char* nstage = smem + OFF_A + ((c + 1) & 1) * A_STAGE;

        float4 pf[4];
        if (c < NCH - 1) {
#pragma unroll
            for (int j = 0; j < 4; j++)
                pf[j] = *reinterpret_cast<const float4*>(
                    ag + (c + 1) * 64 + j * 2 * KD);
        }

#pragma unroll
        for (int s = 0; s < 2; s++) {
            const uint32_t ksa = (((uint32_t)s * 32) + a_csel) ^ xorv;
            const uint32_t ksb = (((uint32_t)s * 32) + b_csel) ^ xorv;
            uint32_t a[4][4], b[2][4];
#pragma unroll
            for (int mf = 0; mf < 4; mf++)
                ldsm_x4(a[mf], abase + (a_row + mf * 16) * 128 + ksa);
#pragma unroll
            for (int nfp = 0; nfp < 2; nfp++)
                ldsm_x4(b[nfp], wbase + (b_row + nfp * 16) * 128 + ksb);
#pragma unroll
            for (int mf = 0; mf < 4; mf++)
#pragma unroll
                for (int nfp = 0; nfp < 2; nfp++) {
                    mma_f16(acc[mf][2 * nfp],     a[mf], b[nfp]);
                    mma_f16(acc[mf][2 * nfp + 1], a[mf], b[nfp] + 2);
                }
        }

        if (c < NCH - 1) {
#pragma unroll
            for (int j = 0; j < 4; j++) {
                int row = rbase + 2 * j;
                uint32_t off = (uint32_t)row * 128 +
                               (stscol ^ (uint32_t)((row & 7) << 4));
                *reinterpret_cast<uint2*>(nstage + off) = cvt2(pf[j]);
            }
#pragma unroll
            for (int j = 0; j < 4; j++)
                pf[j] = *reinterpret_cast<const float4*>(
                    ag + (c + 1) * 64 + (4 + j) * 2 * KD);
        }

#pragma unroll
        for (int s = 2; s < 4; s++) {
            const uint32_t ksa = (((uint32_t)s * 32) + a_csel) ^ xorv;
            const uint32_t ksb = (((uint32_t)s * 32) + b_csel) ^ xorv;
            uint32_t a[4][4], b[2][4];
#pragma unroll
            for (int mf = 0; mf < 4; mf++)
                ldsm_x4(a[mf], abase + (a_row + mf * 16) * 128 + ksa);
#pragma unroll
            for (int nfp = 0; nfp < 2; nfp++)
                ldsm_x4(b[nfp], wbase + (b_row + nfp * 16) * 128 + ksb);
#pragma unroll
            for (int mf = 0; mf < 4; mf++)
#pragma unroll
                for (int nfp = 0; nfp < 2; nfp++) {
                    mma_f16(acc[mf][2 * nfp],     a[mf], b[nfp]);
                    mma_f16(acc[mf][2 * nfp + 1], a[mf], b[nfp] + 2);
                }
        }

        if (c < NCH - 1) {
#pragma unroll
            for (int j = 0; j < 4; j++) {
                int row = rbase + 2 * (4 + j);
                uint32_t off = (uint32_t)row * 128 +
                               (stscol ^ (uint32_t)((row & 7) << 4));
                *reinterpret_cast<uint2*>(nstage + off) = cvt2(pf[j]);
            }
            __syncthreads();
        }
    }

    // ---- epilogue: segmented exclusive scan over 8-row blocks + bias ----
    const int p = lane >> 2;                   // block position 0..7
    float be = __ldg(bias + p);
    if (p == 0) be += be;                      // b_eff[0] = 2*bias[0]

#pragma unroll
    for (int mf = 0; mf < 4; mf++) {
#pragma unroll
        for (int nf = 0; nf < 4; nf++) {
            float e[4];
#pragma unroll
            for (int q = 0; q < 4; q++) {
                float v = acc[mf][nf][q];
                float sgm = v, t;
                t = __shfl_up_sync(0xffffffffu, sgm, 4);  if (p >= 1) sgm += t;
                t = __shfl_up_sync(0xffffffffu, sgm, 8);  if (p >= 2) sgm += t;
                t = __shfl_up_sync(0xffffffffu, sgm, 16); if (p >= 4) sgm += t;
                e[q] = sgm - v + be;
            }
            const int row0 = m0 + wm * 64 + mf * 16 + p;
            const int col  = n0 + wn * 32 + nf * 8 + (lane & 3) * 2;
            *reinterpret_cast<float2*>(out + (size_t)row0 * ND + col) =
                make_float2(e[0], e[1]);
            *reinterpret_cast<float2*>(out + (size_t)(row0 + 8) * ND + col) =
                make_float2(e[2], e[3]);
        }
    }
}

// ---------------------------------------------------------------------------
extern "C" void kernel_launch(void* const* d_in, const int* in_sizes, int n_in,
                              void* d_out, int out_size)
{
    const float* A    = (const float*)d_in[0];   // [65536, 256]
    const float* W    = (const float*)d_in[1];   // [256, 256]
    const float* bias = (const float*)d_in[2];   // [8]
    float* out = (float*)d_out;

    cudaFuncSetAttribute(bc_mma, cudaFuncAttributeMaxDynamicSharedMemorySize,
                         SMEM_TOTAL);
    dim3 grid(ND / BN, MROWS / BM);              // (2, 512)
    bc_mma<<<grid, THREADS, SMEM_TOTAL>>>(A, W, bias, out);
    (void)in_sizes; (void)n_in; (void)out_size;
}

// round 11
// speedup vs baseline: 1.1399x; 1.0536x over previous
#include <cuda_runtime.h>
#include <cuda_fp16.h>
#include <cstdint>

// ============================================================================
// BlockConvolutionLean, fp16 mma.sync, PERSISTENT single kernel:
//   out = segmented-exclusive-cumsum_8( A @ W^T ) + b_eff, b_eff[0]=2*bias[0]
// - Grid = 304 CTAs (2/SM on 152-SM GB300). CTA fixes an N-half (128 cols),
//   converts its W slice fp32->fp16 into smem ONCE, then loops over M-tiles.
// - A: full-line LDG.128 -> cvt f16x2 -> swizzled STS -> ldmatrix; 2-stage;
//   chunk stream is continuous across tiles (chunk 3 prefetches next tile's
//   chunk 0), one __syncthreads per chunk.
// - BN=128 => acc 64 regs/thread => 2 CTAs/SM (16 warps).
// ============================================================================

#define MROWS 65536
#define KD 256
#define ND 256
#define BM 128
#define BN 128
#define THREADS 256
#define NCH 4                          // K chunks of 64
#define TILES_M (MROWS / BM)           // 512
#define NSM 152
#define GRID (2 * NSM)                 // 304; CTA covers n-half + strided m

#define W_REGION 16384                 // 128 rows x 128B (one K=64 chunk)
#define OFF_A (4 * W_REGION)           // 65536: W resident (4 regions)
#define A_STAGE 16384                  // 128 rows x 128B
#define SMEM_TOTAL (OFF_A + 2 * A_STAGE)   // 98304 B -> 2 CTAs = 192KB

// ---------------------------------------------------------------------------
__device__ __forceinline__ uint32_t smem_u32(const void* p) {
    uint32_t a;
    asm("{ .reg .u64 t; cvta.to.shared.u64 t, %1; cvt.u32.u64 %0, t; }"
        : "=r"(a) : "l"(p));
    return a;
}
__device__ __forceinline__ void ldsm_x4(uint32_t* r, uint32_t addr) {
    asm volatile("ldmatrix.sync.aligned.m8n8.x4.shared.b16 {%0,%1,%2,%3}, [%4];"
                 : "=r"(r[0]), "=r"(r[1]), "=r"(r[2]), "=r"(r[3]) : "r"(addr));
}
__device__ __forceinline__ void mma_f16(float* c, const uint32_t* a, const uint32_t* b) {
    asm volatile("mma.sync.aligned.m16n8k16.row.col.f32.f16.f16.f32 "
                 "{%0,%1,%2,%3}, {%4,%5,%6,%7}, {%8,%9}, {%0,%1,%2,%3};"
                 : "+f"(c[0]), "+f"(c[1]), "+f"(c[2]), "+f"(c[3])
                 : "r"(a[0]), "r"(a[1]), "r"(a[2]), "r"(a[3]), "r"(b[0]), "r"(b[1]));
}
__device__ __forceinline__ uint32_t h2u(__half2 h) {
    return *reinterpret_cast<uint32_t*>(&h);
}
__device__ __forceinline__ uint2 cvt2(float4 v) {
    __half2 h0 = __floats2half2_rn(v.x, v.y);
    __half2 h1 = __floats2half2_rn(v.z, v.w);
    return make_uint2(h2u(h0), h2u(h1));
}

// ---------------------------------------------------------------------------
__global__ __launch_bounds__(THREADS, 2)
void bc_mma(const float* __restrict__ A, const float* __restrict__ W,
            const float* __restrict__ bias, float* __restrict__ out)
{
    extern __shared__ __align__(1024) char smem[];
    const int tid = threadIdx.x;
    const int lane = tid & 31, w = tid >> 5;
    const int wm = w >> 2, wn = w & 3;         // 2(m) x 4(n); warp tile 64 x 32
    const int n0 = (blockIdx.x & 1) * BN;      // fixed N-half for this CTA
    const int mseq = blockIdx.x >> 1;          // 0..NSM-1

    // ---- W prologue (ONCE): fp32 LDG -> cvt -> swizzled STS, 4 K-regions ----
    {
        const float* wg = W + (size_t)n0 * KD;
#pragma unroll
        for (int i = 0; i < 32; i++) {
            int v = tid + i * THREADS;         // 0..8191
            int r = v >> 6;                    // W row 0..127
            int f4 = v & 63;                   // float4 index within row
            float4 wv = *reinterpret_cast<const float4*>(
                wg + (size_t)r * KD + f4 * 4);
            int c = f4 >> 4;                   // region 0..3
            uint32_t col = (uint32_t)(f4 & 15) * 8;
            uint32_t off = (uint32_t)c * W_REGION + (uint32_t)r * 128 +
                           (col ^ (uint32_t)((r & 7) << 4));
            *reinterpret_cast<uint2*>(smem + off) = cvt2(wv);
        }
    }

    // ---- per-thread constants ----
    const int rbase = w * 16 + (lane >> 4);    // CTA-local A row
    const uint32_t stscol = (uint32_t)(lane & 15) * 8;
    const uint32_t sb = smem_u32(smem);
    const uint32_t xorv   = (uint32_t)(lane & 7) << 4;
    const uint32_t a_row  = (uint32_t)(wm * 64 + (lane & 15));
    const uint32_t a_csel = ((uint32_t)(lane >> 4)) << 4;
    const uint32_t b_row  = (uint32_t)(wn * 32 + ((lane >> 4) << 3) + (lane & 7));
    const uint32_t b_csel = ((uint32_t)((lane >> 3) & 1)) << 4;

    const int p = lane >> 2;                   // block position 0..7
    float be = __ldg(bias + p);
    if (p == 0) be += be;                      // b_eff[0] = 2*bias[0]

    // A thread offset within a tile
    const size_t a_toff = (size_t)rbase * KD + (lane & 15) * 4;

    // ---- first tile's chunk 0: LDG -> cvt -> STS stage 0 ----
    int mt = mseq;
    {
        const float* ag = A + (size_t)mt * BM * KD + a_toff;
        uint2 pc[8];
#pragma unroll
        for (int j = 0; j < 8; j++)
            pc[j] = cvt2(*reinterpret_cast<const float4*>(ag + j * 2 * KD));
#pragma unroll
        for (int j = 0; j < 8; j++) {
            int row = rbase + 2 * j;
            uint32_t off = (uint32_t)row * 128 + (stscol ^ (uint32_t)((row & 7) << 4));
            *reinterpret_cast<uint2*>(smem + OFF_A + off) = pc[j];
        }
    }
    __syncthreads();

    float acc[4][4][4] = {};

    // ---- persistent tile loop ----
    for (; mt < TILES_M; mt += NSM) {
        const int m0 = mt * BM;
        const float* ag = A + (size_t)m0 * KD + a_toff;
        const int mt_next = mt + NSM;
        const bool has_next = (mt_next < TILES_M);
        const float* ag_next = A + (size_t)mt_next * BM * KD + a_toff;

#pragma unroll
        for (int c = 0; c < NCH; c++) {
            const uint32_t abase = sb + OFF_A + (uint32_t)(c & 1) * A_STAGE;
            const uint32_t wbase = sb + (uint32_t)c * W_REGION;
            char* nstage = smem + OFF_A + ((c + 1) & 1) * A_STAGE;

            // source of the next chunk's A data (crosses into next tile at c=3)
            const bool do_pre = (c < NCH - 1) || has_next;
            const float* src = (c < NCH - 1) ? (ag + (c + 1) * 64) : ag_next;

            float4 pf[4];
            if (do_pre) {
#pragma unroll
                for (int j = 0; j < 4; j++)
                    pf[j] = *reinterpret_cast<const float4*>(src + j * 2 * KD);
            }

#pragma unroll
            for (int s = 0; s < 2; s++) {
                const uint32_t ksa = (((uint32_t)s * 32) + a_csel) ^ xorv;
                const uint32_t ksb = (((uint32_t)s * 32) + b_csel) ^ xorv;
                uint32_t a[4][4], b[2][4];
#pragma unroll
                for (int mf = 0; mf < 4; mf++)
                    ldsm_x4(a[mf], abase + (a_row + mf * 16) * 128 + ksa);
#pragma unroll
                for (int nfp = 0; nfp < 2; nfp++)
                    ldsm_x4(b[nfp], wbase + (b_row + nfp * 16) * 128 + ksb);
#pragma unroll
                for (int mf = 0; mf < 4; mf++)
#pragma unroll
                    for (int nfp = 0; nfp < 2; nfp++) {
                        mma_f16(acc[mf][2 * nfp],     a[mf], b[nfp]);
                        mma_f16(acc[mf][2 * nfp + 1], a[mf], b[nfp] + 2);
                    }
            }

            if (do_pre) {
#pragma unroll
                for (int j = 0; j < 4; j++) {
                    int row = rbase + 2 * j;
                    uint32_t off = (uint32_t)row * 128 +
                                   (stscol ^ (uint32_t)((row & 7) << 4));
                    *reinterpret_cast<uint2*>(nstage + off) = cvt2(pf[j]);
                }
#pragma unroll
                for (int j = 0; j < 4; j++)
                    pf[j] = *reinterpret_cast<const float4*>(src + (4 + j) * 2 * KD);
            }

#pragma unroll
            for (int s = 2; s < 4; s++) {
                const uint32_t ksa = (((uint32_t)s * 32) + a_csel) ^ xorv;
                const uint32_t ksb = (((uint32_t)s * 32) + b_csel) ^ xorv;
                uint32_t a[4][4], b[2][4];
#pragma unroll
                for (int mf = 0; mf < 4; mf++)
                    ldsm_x4(a[mf], abase + (a_row + mf * 16) * 128 + ksa);
#pragma unroll
                for (int nfp = 0; nfp < 2; nfp++)
                    ldsm_x4(b[nfp], wbase + (b_row + nfp * 16) * 128 + ksb);
#pragma unroll
                for (int mf = 0; mf < 4; mf++)
#pragma unroll
                    for (int nfp = 0; nfp < 2; nfp++) {
                        mma_f16(acc[mf][2 * nfp],     a[mf], b[nfp]);
                        mma_f16(acc[mf][2 * nfp + 1], a[mf], b[nfp] + 2);
                    }
            }

            if (do_pre) {
#pragma unroll
                for (int j = 0; j < 4; j++) {
                    int row = rbase + 2 * (4 + j);
                    uint32_t off = (uint32_t)row * 128 +
                                   (stscol ^ (uint32_t)((row & 7) << 4));
                    *reinterpret_cast<uint2*>(nstage + off) = cvt2(pf[j]);
                }
            }
            __syncthreads();
        }

        // ---- epilogue: segmented exclusive scan + bias + STG; reset acc ----
#pragma unroll
        for (int mf = 0; mf < 4; mf++) {
#pragma unroll
            for (int nf = 0; nf < 4; nf++) {
                float e[4];
#pragma unroll
                for (int q = 0; q < 4; q++) {
                    float v = acc[mf][nf][q];
                    float sgm = v, t;
                    t = __shfl_up_sync(0xffffffffu, sgm, 4);  if (p >= 1) sgm += t;
                    t = __shfl_up_sync(0xffffffffu, sgm, 8);  if (p >= 2) sgm += t;
                    t = __shfl_up_sync(0xffffffffu, sgm, 16); if (p >= 4) sgm += t;
                    e[q] = sgm - v + be;
                    acc[mf][nf][q] = 0.f;
                }
                const int row0 = m0 + wm * 64 + mf * 16 + p;
                const int col  = n0 + wn * 32 + nf * 8 + (lane & 3) * 2;
                *reinterpret_cast<float2*>(out + (size_t)row0 * ND + col) =
                    make_float2(e[0], e[1]);
                *reinterpret_cast<float2*>(out + (size_t)(row0 + 8) * ND + col) =
                    make_float2(e[2], e[3]);
            }
        }
    }
}

// ---------------------------------------------------------------------------
extern "C" void kernel_launch(void* const* d_in, const int* in_sizes, int n_in,
                              void* d_out, int out_size)
{
    const float* A    = (const float*)d_in[0];   // [65536, 256]
    const float* W    = (const float*)d_in[1];   // [256, 256]
    const float* bias = (const float*)d_in[2];   // [8]
    float* out = (float*)d_out;

    cudaFuncSetAttribute(bc_mma, cudaFuncAttributeMaxDynamicSharedMemorySize,
                         SMEM_TOTAL);
    bc_mma<<<GRID, THREADS, SMEM_TOTAL>>>(A, W, bias, out);
    (void)in_sizes; (void)n_in; (void)out_size;
}